// round 2
// baseline (speedup 1.0000x reference)
#include <cuda_runtime.h>
#include <math.h>

#define BATCH 2
#define SEQ   2048
#define DM    1024
#define NH    16
#define DH    64
#define MROWS (BATCH*SEQ)   // 4096

// Scratch (static device globals; no allocations allowed)
__device__ float g_xn[MROWS*DM];
__device__ float g_q [MROWS*DM];
__device__ float g_k [MROWS*DM];
__device__ float g_v [MROWS*DM];
__device__ float g_o [MROWS*DM];

// ---------------------------------------------------------------------------
// LayerNorm: one block per row, 256 threads, float4 vectorized
// ---------------------------------------------------------------------------
__global__ __launch_bounds__(256) void ln_kernel(const float* __restrict__ x,
                                                 const float* __restrict__ gamma,
                                                 const float* __restrict__ beta,
                                                 float* __restrict__ xn)
{
    int row = blockIdx.x;
    int tid = threadIdx.x;
    const float4* xr = (const float4*)(x + (size_t)row * DM);
    float4 v = xr[tid];
    float s  = v.x + v.y + v.z + v.w;
    float ss = v.x*v.x + v.y*v.y + v.z*v.z + v.w*v.w;
    #pragma unroll
    for (int o = 16; o; o >>= 1) {
        s  += __shfl_down_sync(0xffffffffu, s,  o);
        ss += __shfl_down_sync(0xffffffffu, ss, o);
    }
    __shared__ float sb[8], ssb[8];
    __shared__ float mean_s, inv_s;
    int warp = tid >> 5, lane = tid & 31;
    if (lane == 0) { sb[warp] = s; ssb[warp] = ss; }
    __syncthreads();
    if (tid == 0) {
        float S = 0.f, SS = 0.f;
        #pragma unroll
        for (int i = 0; i < 8; i++) { S += sb[i]; SS += ssb[i]; }
        float mean = S * (1.0f / DM);
        float var  = SS * (1.0f / DM) - mean * mean;
        mean_s = mean;
        inv_s  = rsqrtf(var + 1e-5f);
    }
    __syncthreads();
    float mean = mean_s, inv = inv_s;
    float4 g = ((const float4*)gamma)[tid];
    float4 b = ((const float4*)beta)[tid];
    float4 o;
    o.x = (v.x - mean) * inv * g.x + b.x;
    o.y = (v.y - mean) * inv * g.y + b.y;
    o.z = (v.z - mean) * inv * g.z + b.z;
    o.w = (v.w - mean) * inv * g.w + b.w;
    ((float4*)(xn + (size_t)row * DM))[tid] = o;
}

// ---------------------------------------------------------------------------
// SGEMM: C[M,N] = A[M,K] @ B[K,N] (+ bias[N]) (+ resid[M,N])
// 128x128 tile, BK=8, 16x16 threads, 8x8 per-thread microtile
// ---------------------------------------------------------------------------
__global__ __launch_bounds__(256) void sgemm_kernel(const float* __restrict__ A,
                                                    const float* __restrict__ Bm,
                                                    float* __restrict__ C,
                                                    int M, int N, int K,
                                                    const float* __restrict__ bias,
                                                    const float* __restrict__ resid)
{
    __shared__ float As[8][128];   // transposed A tile
    __shared__ float Bs[8][128];
    int tx = threadIdx.x, ty = threadIdx.y;   // 16x16
    int tid = ty * 16 + tx;
    int row0 = blockIdx.y * 128, col0 = blockIdx.x * 128;

    float acc[8][8];
    #pragma unroll
    for (int i = 0; i < 8; i++)
        #pragma unroll
        for (int j = 0; j < 8; j++) acc[i][j] = 0.f;

    int ar = tid >> 1,  ac = (tid & 1) * 4;    // A: 128 rows x 8 cols
    int br = tid >> 5,  bc = (tid & 31) * 4;   // B: 8 rows x 128 cols
    const float* Aptr = A  + (size_t)(row0 + ar) * K + ac;
    const float* Bptr = Bm + (size_t)br * N + col0 + bc;

    for (int k0 = 0; k0 < K; k0 += 8) {
        float4 av = *(const float4*)(Aptr + k0);
        float4 bv = *(const float4*)(Bptr + (size_t)k0 * N);
        As[ac + 0][ar] = av.x;
        As[ac + 1][ar] = av.y;
        As[ac + 2][ar] = av.z;
        As[ac + 3][ar] = av.w;
        *(float4*)&Bs[br][bc] = bv;
        __syncthreads();
        #pragma unroll
        for (int kk = 0; kk < 8; kk++) {
            float a[8], b[8];
            *(float4*)(a)     = *(const float4*)&As[kk][ty * 8];
            *(float4*)(a + 4) = *(const float4*)&As[kk][ty * 8 + 4];
            *(float4*)(b)     = *(const float4*)&Bs[kk][tx * 8];
            *(float4*)(b + 4) = *(const float4*)&Bs[kk][tx * 8 + 4];
            #pragma unroll
            for (int i = 0; i < 8; i++)
                #pragma unroll
                for (int j = 0; j < 8; j++)
                    acc[i][j] += a[i] * b[j];
        }
        __syncthreads();
    }

    #pragma unroll
    for (int i = 0; i < 8; i++) {
        int r = row0 + ty * 8 + i;
        float* Crow = C + (size_t)r * N + col0 + tx * 8;
        #pragma unroll
        for (int j = 0; j < 8; j += 4) {
            float4 o;
            o.x = acc[i][j + 0];
            o.y = acc[i][j + 1];
            o.z = acc[i][j + 2];
            o.w = acc[i][j + 3];
            if (bias) {
                float4 bvv = *(const float4*)(bias + col0 + tx * 8 + j);
                o.x += bvv.x; o.y += bvv.y; o.z += bvv.z; o.w += bvv.w;
            }
            if (resid) {
                float4 rv = *(const float4*)(resid + (size_t)r * N + col0 + tx * 8 + j);
                o.x += rv.x; o.y += rv.y; o.z += rv.z; o.w += rv.w;
            }
            *(float4*)(Crow + j) = o;
        }
    }
}

// ---------------------------------------------------------------------------
// Flash-style causal attention.
// Grid: (T/64, B*H). Block: 256 threads = 8 warps; warp w owns 8 query rows.
// Q/K/V layout [B, T, H*DH]. K stored transposed in smem for conflict-free
// score LDS; P broadcast through shuffles for the P@V accumulation.
// ---------------------------------------------------------------------------
__global__ __launch_bounds__(256) void attn_kernel(const float* __restrict__ Q,
                                                   const float* __restrict__ K,
                                                   const float* __restrict__ V,
                                                   float* __restrict__ O)
{
    __shared__ float Qs [64 * 64];
    __shared__ float Kst[64 * 64];   // [d][k]
    __shared__ float Vs [64 * 64];   // [k][d]

    int qt  = blockIdx.x;
    int bh  = blockIdx.y;
    int b   = bh >> 4;
    int h   = bh & 15;
    int tid = threadIdx.x;
    int warp = tid >> 5, lane = tid & 31;
    int q0 = qt * 64;

    // Load Q tile [64 x 64]
    {
        int r  = tid >> 2;
        int c0 = (tid & 3) * 16;
        const float* src = Q + ((size_t)(b * SEQ + q0 + r) * DM + h * DH + c0);
        #pragma unroll
        for (int i = 0; i < 4; i++)
            *(float4*)&Qs[r * 64 + c0 + 4 * i] = *(const float4*)(src + 4 * i);
    }

    float o0[8], o1[8], mrow[8], lrow[8];
    #pragma unroll
    for (int i = 0; i < 8; i++) { o0[i] = 0.f; o1[i] = 0.f; mrow[i] = -1e30f; lrow[i] = 0.f; }

    for (int kt = 0; kt <= qt; ++kt) {
        int k0 = kt * 64;
        __syncthreads();   // protect previous tile's smem reads
        {
            int r  = tid >> 2;
            int c0 = (tid & 3) * 16;
            const float* ksrc = K + ((size_t)(b * SEQ + k0 + r) * DM + h * DH + c0);
            const float* vsrc = V + ((size_t)(b * SEQ + k0 + r) * DM + h * DH + c0);
            #pragma unroll
            for (int i = 0; i < 4; i++) {
                float4 kv = *(const float4*)(ksrc + 4 * i);
                Kst[(c0 + 4 * i + 0) * 64 + r] = kv.x;
                Kst[(c0 + 4 * i + 1) * 64 + r] = kv.y;
                Kst[(c0 + 4 * i + 2) * 64 + r] = kv.z;
                Kst[(c0 + 4 * i + 3) * 64 + r] = kv.w;
                *(float4*)&Vs[r * 64 + c0 + 4 * i] = *(const float4*)(vsrc + 4 * i);
            }
        }
        __syncthreads();

        // Scores: warp handles rows q0+warp*8 .. +7, lane handles keys lane, lane+32
        float s0[8], s1[8];
        #pragma unroll
        for (int i = 0; i < 8; i++) { s0[i] = 0.f; s1[i] = 0.f; }
        #pragma unroll 8
        for (int d = 0; d < 64; ++d) {
            float kv0 = Kst[d * 64 + lane];
            float kv1 = Kst[d * 64 + lane + 32];
            #pragma unroll
            for (int i = 0; i < 8; i++) {
                float qv = Qs[(warp * 8 + i) * 64 + d];
                s0[i] += qv * kv0;
                s1[i] += qv * kv1;
            }
        }

        // Online softmax update per row
        float p0s[8], p1s[8];
        #pragma unroll
        for (int i = 0; i < 8; i++) {
            int q = q0 + warp * 8 + i;
            float a = s0[i] * 0.125f;
            float c = s1[i] * 0.125f;
            if (kt == qt) {
                if (k0 + lane      > q) a = -1e30f;
                if (k0 + lane + 32 > q) c = -1e30f;
            }
            float mloc = fmaxf(a, c);
            #pragma unroll
            for (int off = 16; off; off >>= 1)
                mloc = fmaxf(mloc, __shfl_xor_sync(0xffffffffu, mloc, off));
            float mnew  = fmaxf(mrow[i], mloc);
            float alpha = __expf(mrow[i] - mnew);
            float p0 = __expf(a - mnew);
            float p1 = __expf(c - mnew);
            float psum = p0 + p1;
            #pragma unroll
            for (int off = 16; off; off >>= 1)
                psum += __shfl_xor_sync(0xffffffffu, psum, off);
            lrow[i] = lrow[i] * alpha + psum;
            mrow[i] = mnew;
            o0[i] *= alpha;
            o1[i] *= alpha;
            p0s[i] = p0;
            p1s[i] = p1;
        }

        // O += P @ V ; lane owns dims lane, lane+32
        #pragma unroll 4
        for (int k = 0; k < 64; k++) {
            float vv0 = Vs[k * 64 + lane];
            float vv1 = Vs[k * 64 + lane + 32];
            int src = k & 31;
            #pragma unroll
            for (int i = 0; i < 8; i++) {
                float pk = __shfl_sync(0xffffffffu, (k < 32) ? p0s[i] : p1s[i], src);
                o0[i] += pk * vv0;
                o1[i] += pk * vv1;
            }
        }
    }

    #pragma unroll
    for (int i = 0; i < 8; i++) {
        int q = q0 + warp * 8 + i;
        float inv = 1.f / lrow[i];
        float* dst = O + ((size_t)(b * SEQ + q) * DM + h * DH);
        dst[lane]      = o0[i] * inv;
        dst[lane + 32] = o1[i] * inv;
    }
}

// ---------------------------------------------------------------------------
extern "C" void kernel_launch(void* const* d_in, const int* in_sizes, int n_in,
                              void* d_out, int out_size)
{
    const float* x     = (const float*)d_in[0];
    const float* Wq    = (const float*)d_in[1];
    const float* Wk    = (const float*)d_in[2];
    const float* Wv    = (const float*)d_in[3];
    const float* Wo    = (const float*)d_in[4];
    const float* bo    = (const float*)d_in[5];
    const float* gamma = (const float*)d_in[6];
    const float* beta  = (const float*)d_in[7];
    // d_in[8] = mask (causal, known statically; unused)
    float* out = (float*)d_out;

    // One-time symbol address resolution (host-side, deterministic, capture-safe)
    static float *xn = nullptr, *q = nullptr, *k = nullptr, *v = nullptr, *o = nullptr;
    if (!xn) {
        cudaGetSymbolAddress((void**)&xn, g_xn);
        cudaGetSymbolAddress((void**)&q,  g_q);
        cudaGetSymbolAddress((void**)&k,  g_k);
        cudaGetSymbolAddress((void**)&v,  g_v);
        cudaGetSymbolAddress((void**)&o,  g_o);
    }

    ln_kernel<<<MROWS, 256>>>(x, gamma, beta, xn);

    dim3 gblock(16, 16);
    dim3 ggrid(DM / 128, MROWS / 128);
    sgemm_kernel<<<ggrid, gblock>>>(xn, Wq, q, MROWS, DM, DM, nullptr, nullptr);
    sgemm_kernel<<<ggrid, gblock>>>(xn, Wk, k, MROWS, DM, DM, nullptr, nullptr);
    sgemm_kernel<<<ggrid, gblock>>>(xn, Wv, v, MROWS, DM, DM, nullptr, nullptr);

    attn_kernel<<<dim3(SEQ / 64, BATCH * NH), 256>>>(q, k, v, o);

    sgemm_kernel<<<ggrid, gblock>>>(o, Wo, out, MROWS, DM, DM, bo, xn);
}

// round 14
// speedup vs baseline: 1.2113x; 1.2113x over previous
#include <cuda_runtime.h>
#include <cstdint>
#include <math.h>

#define BATCH 2
#define SEQ   2048
#define DM    1024
#define NH    16
#define DH    64
#define MROWS (BATCH*SEQ)   // 4096

// Scratch (static device globals; no allocations allowed)
__device__ float g_xn[MROWS*DM];
__device__ float g_q [MROWS*DM];
__device__ float g_k [MROWS*DM];
__device__ float g_v [MROWS*DM];
__device__ float g_o [MROWS*DM];

// ---------------------------------------------------------------------------
// Helpers
// ---------------------------------------------------------------------------
__device__ __forceinline__ uint32_t f2tf32(float f) {
    uint32_t r;
    asm("cvt.rna.tf32.f32 %0, %1;" : "=r"(r) : "f"(f));
    return r;
}

__device__ __forceinline__ void mma_tf32(float* c, const uint32_t* a, const uint32_t* b) {
    asm volatile(
        "mma.sync.aligned.m16n8k8.row.col.f32.tf32.tf32.f32 "
        "{%0,%1,%2,%3}, {%4,%5,%6,%7}, {%8,%9}, {%0,%1,%2,%3};"
        : "+f"(c[0]), "+f"(c[1]), "+f"(c[2]), "+f"(c[3])
        : "r"(a[0]), "r"(a[1]), "r"(a[2]), "r"(a[3]), "r"(b[0]), "r"(b[1]));
}

// ---------------------------------------------------------------------------
// mma.sync tf32 GEMM: C[M,N] = A[M,K] @ B[K,N] (+bias) (+resid)
// 128x128 CTA tile, 8 warps of 64x32, KC=32, double-buffered smem.
// As: [m][k] stride 36 floats (frag bank = 4g+tg, conflict-free)
// Bs: [k][n] stride 136 floats (frag bank = 8tg+g, conflict-free)
// blockIdx.z selects among up to 3 (B, C) pairs (fused QKV).
// ---------------------------------------------------------------------------
#define KC        32
#define NITER     (DM / KC)     // 32
#define AS_STRIDE 36
#define BS_STRIDE 136
#define AS_ELEMS  (128 * AS_STRIDE)   // 4608
#define BS_ELEMS  (KC * BS_STRIDE)    // 4352
#define GEMM_SMEM_BYTES ((2 * AS_ELEMS + 2 * BS_ELEMS) * 4)   // 71680

// A: 128 rows x 32 k-floats; idx = tid*4+i -> m = idx>>3, seg = idx&7
// B: 32 k-rows x 128 n-floats; idx -> k = idx>>5, seg = idx&31
__device__ __forceinline__ void load_tile(const float* __restrict__ A,
                                          const float* __restrict__ B,
                                          int row0, int col0, int kc, int tid,
                                          float4* ar, float4* br)
{
    #pragma unroll
    for (int i = 0; i < 4; i++) {
        int idx = tid * 4 + i;
        int m = idx >> 3, seg = idx & 7;
        ar[i] = *(const float4*)(A + (size_t)(row0 + m) * DM + kc + seg * 4);
        int k = idx >> 5, sg2 = idx & 31;
        br[i] = *(const float4*)(B + (size_t)(kc + k) * DM + col0 + sg2 * 4);
    }
}

__device__ __forceinline__ void store_tile(uint32_t* __restrict__ Abuf,
                                           uint32_t* __restrict__ Bbuf,
                                           int tid, const float4* ar, const float4* br)
{
    #pragma unroll
    for (int i = 0; i < 4; i++) {
        int idx = tid * 4 + i;
        int m = idx >> 3, seg = idx & 7;
        uint4 pa;
        pa.x = f2tf32(ar[i].x); pa.y = f2tf32(ar[i].y);
        pa.z = f2tf32(ar[i].z); pa.w = f2tf32(ar[i].w);
        *(uint4*)&Abuf[m * AS_STRIDE + seg * 4] = pa;
        int k = idx >> 5, sg2 = idx & 31;
        uint4 pb;
        pb.x = f2tf32(br[i].x); pb.y = f2tf32(br[i].y);
        pb.z = f2tf32(br[i].z); pb.w = f2tf32(br[i].w);
        *(uint4*)&Bbuf[k * BS_STRIDE + sg2 * 4] = pb;
    }
}

__global__ void __launch_bounds__(256) gemm_mma_kernel(const float* __restrict__ A,
                                                       const float* __restrict__ B0,
                                                       const float* __restrict__ B1,
                                                       const float* __restrict__ B2,
                                                       float* __restrict__ C0,
                                                       float* __restrict__ C1,
                                                       float* __restrict__ C2,
                                                       const float* __restrict__ bias,
                                                       const float* __restrict__ resid)
{
    extern __shared__ uint32_t smu[];
    uint32_t* Asm[2] = { smu,                smu + AS_ELEMS };
    uint32_t* Bsm[2] = { smu + 2 * AS_ELEMS, smu + 2 * AS_ELEMS + BS_ELEMS };

    int tid  = threadIdx.x;
    int lane = tid & 31;
    int warp = tid >> 5;            // 0..7
    int g    = lane >> 2;           // 0..7
    int tg   = lane & 3;            // 0..3
    int wmi  = warp >> 2;           // 0..1 -> M offset wmi*64
    int wni  = warp & 3;            // 0..3 -> N offset wni*32

    int row0 = blockIdx.y * 128, col0 = blockIdx.x * 128;
    int mz = blockIdx.z;
    const float* B = (mz == 0) ? B0 : (mz == 1) ? B1 : B2;
    float*       C = (mz == 0) ? C0 : (mz == 1) ? C1 : C2;

    float acc[4][4][4];
    #pragma unroll
    for (int mt = 0; mt < 4; mt++)
        #pragma unroll
        for (int nt = 0; nt < 4; nt++)
            #pragma unroll
            for (int i = 0; i < 4; i++) acc[mt][nt][i] = 0.f;

    float4 ar[4], br[4];

    // prologue
    load_tile(A, B, row0, col0, 0, tid, ar, br);
    store_tile(Asm[0], Bsm[0], tid, ar, br);
    __syncthreads();

    for (int it = 0; it < NITER; ++it) {
        int s = it & 1;
        if (it + 1 < NITER) load_tile(A, B, row0, col0, (it + 1) * KC, tid, ar, br);

        const uint32_t* As = Asm[s];
        const uint32_t* Bs = Bsm[s];
        #pragma unroll
        for (int k8 = 0; k8 < KC / 8; k8++) {
            int kb = k8 * 8;
            uint32_t af[4][4];
            #pragma unroll
            for (int mt = 0; mt < 4; mt++) {
                int mr = wmi * 64 + mt * 16;
                af[mt][0] = As[(mr + g)      * AS_STRIDE + kb + tg];
                af[mt][1] = As[(mr + 8 + g)  * AS_STRIDE + kb + tg];
                af[mt][2] = As[(mr + g)      * AS_STRIDE + kb + tg + 4];
                af[mt][3] = As[(mr + 8 + g)  * AS_STRIDE + kb + tg + 4];
            }
            uint32_t bf[4][2];
            #pragma unroll
            for (int nt = 0; nt < 4; nt++) {
                int nc = wni * 32 + nt * 8;
                bf[nt][0] = Bs[(kb + tg)     * BS_STRIDE + nc + g];
                bf[nt][1] = Bs[(kb + tg + 4) * BS_STRIDE + nc + g];
            }
            #pragma unroll
            for (int mt = 0; mt < 4; mt++)
                #pragma unroll
                for (int nt = 0; nt < 4; nt++)
                    mma_tf32(acc[mt][nt], af[mt], bf[nt]);
        }

        if (it + 1 < NITER) store_tile(Asm[(it + 1) & 1], Bsm[(it + 1) & 1], tid, ar, br);
        __syncthreads();
    }

    // ---- epilogue: frag -> gmem (float2 per half-tile row) ----
    #pragma unroll
    for (int mt = 0; mt < 4; mt++) {
        #pragma unroll
        for (int nt = 0; nt < 4; nt++) {
            int r = row0 + wmi * 64 + mt * 16 + g;
            int c = col0 + wni * 32 + nt * 8 + tg * 2;
            float2 v0 = make_float2(acc[mt][nt][0], acc[mt][nt][1]);
            float2 v1 = make_float2(acc[mt][nt][2], acc[mt][nt][3]);
            if (bias) {
                float2 bb = *(const float2*)(bias + c);
                v0.x += bb.x; v0.y += bb.y;
                v1.x += bb.x; v1.y += bb.y;
            }
            if (resid) {
                float2 r0 = *(const float2*)(resid + (size_t)r * DM + c);
                float2 r1 = *(const float2*)(resid + (size_t)(r + 8) * DM + c);
                v0.x += r0.x; v0.y += r0.y;
                v1.x += r1.x; v1.y += r1.y;
            }
            *(float2*)(C + (size_t)r * DM + c)       = v0;
            *(float2*)(C + (size_t)(r + 8) * DM + c) = v1;
        }
    }
}

// ---------------------------------------------------------------------------
// LayerNorm: one block per row, 256 threads, float4 vectorized
// ---------------------------------------------------------------------------
__global__ __launch_bounds__(256) void ln_kernel(const float* __restrict__ x,
                                                 const float* __restrict__ gamma,
                                                 const float* __restrict__ beta,
                                                 float* __restrict__ xn)
{
    int row = blockIdx.x;
    int tid = threadIdx.x;
    const float4* xr = (const float4*)(x + (size_t)row * DM);
    float4 v = xr[tid];
    float s  = v.x + v.y + v.z + v.w;
    float ss = v.x*v.x + v.y*v.y + v.z*v.z + v.w*v.w;
    #pragma unroll
    for (int o = 16; o; o >>= 1) {
        s  += __shfl_down_sync(0xffffffffu, s,  o);
        ss += __shfl_down_sync(0xffffffffu, ss, o);
    }
    __shared__ float sb[8], ssb[8];
    __shared__ float mean_s, inv_s;
    int warp = tid >> 5, lane = tid & 31;
    if (lane == 0) { sb[warp] = s; ssb[warp] = ss; }
    __syncthreads();
    if (tid == 0) {
        float S = 0.f, SS = 0.f;
        #pragma unroll
        for (int i = 0; i < 8; i++) { S += sb[i]; SS += ssb[i]; }
        float mean = S * (1.0f / DM);
        float var  = SS * (1.0f / DM) - mean * mean;
        mean_s = mean;
        inv_s  = rsqrtf(var + 1e-5f);
    }
    __syncthreads();
    float mean = mean_s, inv = inv_s;
    float4 g = ((const float4*)gamma)[tid];
    float4 b = ((const float4*)beta)[tid];
    float4 o;
    o.x = (v.x - mean) * inv * g.x + b.x;
    o.y = (v.y - mean) * inv * g.y + b.y;
    o.z = (v.z - mean) * inv * g.z + b.z;
    o.w = (v.w - mean) * inv * g.w + b.w;
    ((float4*)(xn + (size_t)row * DM))[tid] = o;
}

// ---------------------------------------------------------------------------
// Flash-style causal attention (fp32). Grid: (T/64, B*H). Block: 256.
// ---------------------------------------------------------------------------
__global__ __launch_bounds__(256) void attn_kernel(const float* __restrict__ Q,
                                                   const float* __restrict__ K,
                                                   const float* __restrict__ V,
                                                   float* __restrict__ O)
{
    __shared__ float Qs [64 * 64];
    __shared__ float Kst[64 * 64];   // [d][k]
    __shared__ float Vs [64 * 64];   // [k][d]

    int qt  = blockIdx.x;
    int bh  = blockIdx.y;
    int b   = bh >> 4;
    int h   = bh & 15;
    int tid = threadIdx.x;
    int warp = tid >> 5, lane = tid & 31;
    int q0 = qt * 64;

    {
        int r  = tid >> 2;
        int c0 = (tid & 3) * 16;
        const float* src = Q + ((size_t)(b * SEQ + q0 + r) * DM + h * DH + c0);
        #pragma unroll
        for (int i = 0; i < 4; i++)
            *(float4*)&Qs[r * 64 + c0 + 4 * i] = *(const float4*)(src + 4 * i);
    }

    float o0[8], o1[8], mrow[8], lrow[8];
    #pragma unroll
    for (int i = 0; i < 8; i++) { o0[i] = 0.f; o1[i] = 0.f; mrow[i] = -1e30f; lrow[i] = 0.f; }

    for (int kt = 0; kt <= qt; ++kt) {
        int k0 = kt * 64;
        __syncthreads();
        {
            int r  = tid >> 2;
            int c0 = (tid & 3) * 16;
            const float* ksrc = K + ((size_t)(b * SEQ + k0 + r) * DM + h * DH + c0);
            const float* vsrc = V + ((size_t)(b * SEQ + k0 + r) * DM + h * DH + c0);
            #pragma unroll
            for (int i = 0; i < 4; i++) {
                float4 kv = *(const float4*)(ksrc + 4 * i);
                Kst[(c0 + 4 * i + 0) * 64 + r] = kv.x;
                Kst[(c0 + 4 * i + 1) * 64 + r] = kv.y;
                Kst[(c0 + 4 * i + 2) * 64 + r] = kv.z;
                Kst[(c0 + 4 * i + 3) * 64 + r] = kv.w;
                *(float4*)&Vs[r * 64 + c0 + 4 * i] = *(const float4*)(vsrc + 4 * i);
            }
        }
        __syncthreads();

        float s0[8], s1[8];
        #pragma unroll
        for (int i = 0; i < 8; i++) { s0[i] = 0.f; s1[i] = 0.f; }
        #pragma unroll 8
        for (int d = 0; d < 64; ++d) {
            float kv0 = Kst[d * 64 + lane];
            float kv1 = Kst[d * 64 + lane + 32];
            #pragma unroll
            for (int i = 0; i < 8; i++) {
                float qv = Qs[(warp * 8 + i) * 64 + d];
                s0[i] += qv * kv0;
                s1[i] += qv * kv1;
            }
        }

        float p0s[8], p1s[8];
        #pragma unroll
        for (int i = 0; i < 8; i++) {
            int q = q0 + warp * 8 + i;
            float a = s0[i] * 0.125f;
            float c = s1[i] * 0.125f;
            if (kt == qt) {
                if (k0 + lane      > q) a = -1e30f;
                if (k0 + lane + 32 > q) c = -1e30f;
            }
            float mloc = fmaxf(a, c);
            #pragma unroll
            for (int off = 16; off; off >>= 1)
                mloc = fmaxf(mloc, __shfl_xor_sync(0xffffffffu, mloc, off));
            float mnew  = fmaxf(mrow[i], mloc);
            float alpha = __expf(mrow[i] - mnew);
            float p0 = __expf(a - mnew);
            float p1 = __expf(c - mnew);
            float psum = p0 + p1;
            #pragma unroll
            for (int off = 16; off; off >>= 1)
                psum += __shfl_xor_sync(0xffffffffu, psum, off);
            lrow[i] = lrow[i] * alpha + psum;
            mrow[i] = mnew;
            o0[i] *= alpha;
            o1[i] *= alpha;
            p0s[i] = p0;
            p1s[i] = p1;
        }

        #pragma unroll 4
        for (int k = 0; k < 64; k++) {
            float vv0 = Vs[k * 64 + lane];
            float vv1 = Vs[k * 64 + lane + 32];
            int src = k & 31;
            #pragma unroll
            for (int i = 0; i < 8; i++) {
                float pk = __shfl_sync(0xffffffffu, (k < 32) ? p0s[i] : p1s[i], src);
                o0[i] += pk * vv0;
                o1[i] += pk * vv1;
            }
        }
    }

    #pragma unroll
    for (int i = 0; i < 8; i++) {
        int q = q0 + warp * 8 + i;
        float inv = 1.f / lrow[i];
        float* dst = O + ((size_t)(b * SEQ + q) * DM + h * DH);
        dst[lane]      = o0[i] * inv;
        dst[lane + 32] = o1[i] * inv;
    }
}

// ---------------------------------------------------------------------------
extern "C" void kernel_launch(void* const* d_in, const int* in_sizes, int n_in,
                              void* d_out, int out_size)
{
    const float* x     = (const float*)d_in[0];
    const float* Wq    = (const float*)d_in[1];
    const float* Wk    = (const float*)d_in[2];
    const float* Wv    = (const float*)d_in[3];
    const float* Wo    = (const float*)d_in[4];
    const float* bo    = (const float*)d_in[5];
    const float* gamma = (const float*)d_in[6];
    const float* beta  = (const float*)d_in[7];
    float* out = (float*)d_out;

    static float *xn = nullptr, *q = nullptr, *k = nullptr, *v = nullptr, *o = nullptr;
    if (!xn) {
        cudaGetSymbolAddress((void**)&xn, g_xn);
        cudaGetSymbolAddress((void**)&q,  g_q);
        cudaGetSymbolAddress((void**)&k,  g_k);
        cudaGetSymbolAddress((void**)&v,  g_v);
        cudaGetSymbolAddress((void**)&o,  g_o);
        cudaFuncSetAttribute(gemm_mma_kernel,
                             cudaFuncAttributeMaxDynamicSharedMemorySize, GEMM_SMEM_BYTES);
    }

    ln_kernel<<<MROWS, 256>>>(x, gamma, beta, xn);

    // Fused QKV: blockIdx.z in {0,1,2} selects (Wq->q, Wk->k, Wv->v)
    dim3 gqkv(DM / 128, MROWS / 128, 3);
    gemm_mma_kernel<<<gqkv, 256, GEMM_SMEM_BYTES>>>(xn, Wq, Wk, Wv, q, k, v,
                                                    nullptr, nullptr);

    attn_kernel<<<dim3(SEQ / 64, BATCH * NH), 256>>>(q, k, v, o);

    dim3 gout(DM / 128, MROWS / 128, 1);
    gemm_mma_kernel<<<gout, 256, GEMM_SMEM_BYTES>>>(o, Wo, nullptr, nullptr, out, nullptr, nullptr,
                                                    bo, xn);
}